// round 2
// baseline (speedup 1.0000x reference)
#include <cuda_runtime.h>

// Problem constants
#define Bd 8
#define Td 512
#define Cd 512
#define NHd 8
#define HDd 64
#define Md (Bd * Td)            // 4096 rows
#define QKVN (3 * Cd)           // 1536

// Scratch (device globals — no allocations allowed)
__device__ float g_qkv[Bd * Td * 3 * Cd];   // [B,T,3C]  (q,k LN'd in place)
__device__ float g_y[Bd * Td * Cd];         // attention output [B,T,C]

// ---------------------------------------------------------------------------
// Generic SGEMM: out[m,n] = sum_k A[m,k] * W[n,k] + bias[n]
// 64x64 tile, BK=16, 256 threads, 4x4 microtile, float4 smem traffic.
// ---------------------------------------------------------------------------
__global__ __launch_bounds__(256) void sgemm_bias_kernel(
    const float* __restrict__ A, const float* __restrict__ W,
    const float* __restrict__ bias, float* __restrict__ out,
    int Kdim, int Ndim)
{
    __shared__ float As[16][68];
    __shared__ float Bs[16][68];
    const int tid = threadIdx.x;
    const int tx = tid & 15, ty = tid >> 4;
    const int m0 = blockIdx.y << 6, n0 = blockIdx.x << 6;

    const int lr = tid >> 2;            // row within tile for loads (0..63)
    const int lk = (tid & 3) << 2;      // k offset (0,4,8,12)

    float acc[4][4] = {};

    for (int k0 = 0; k0 < Kdim; k0 += 16) {
        float4 av = *(const float4*)&A[(size_t)(m0 + lr) * Kdim + k0 + lk];
        float4 bv = *(const float4*)&W[(size_t)(n0 + lr) * Kdim + k0 + lk];
        As[lk + 0][lr] = av.x; As[lk + 1][lr] = av.y;
        As[lk + 2][lr] = av.z; As[lk + 3][lr] = av.w;
        Bs[lk + 0][lr] = bv.x; Bs[lk + 1][lr] = bv.y;
        Bs[lk + 2][lr] = bv.z; Bs[lk + 3][lr] = bv.w;
        __syncthreads();
        #pragma unroll
        for (int kk = 0; kk < 16; kk++) {
            float4 ra = *(const float4*)&As[kk][ty << 2];
            float4 rb = *(const float4*)&Bs[kk][tx << 2];
            float a_[4] = {ra.x, ra.y, ra.z, ra.w};
            float b_[4] = {rb.x, rb.y, rb.z, rb.w};
            #pragma unroll
            for (int i = 0; i < 4; i++)
                #pragma unroll
                for (int j = 0; j < 4; j++)
                    acc[i][j] += a_[i] * b_[j];
        }
        __syncthreads();
    }

    #pragma unroll
    for (int i = 0; i < 4; i++) {
        int m = m0 + (ty << 2) + i;
        #pragma unroll
        for (int j = 0; j < 4; j++) {
            int n = n0 + (tx << 2) + j;
            out[(size_t)m * Ndim + n] = acc[i][j] + bias[n];
        }
    }
}

// ---------------------------------------------------------------------------
// LayerNorm q and k segments of qkv in place. One block per (b,t) row.
// ---------------------------------------------------------------------------
__global__ __launch_bounds__(256) void ln_qk_kernel(
    float* __restrict__ qkv,
    const float* __restrict__ qg, const float* __restrict__ qb,
    const float* __restrict__ kg, const float* __restrict__ kb)
{
    const int bt = blockIdx.x;
    float* row = qkv + (size_t)bt * QKVN;
    const int tid = threadIdx.x;
    const int lane = tid & 31, w = tid >> 5;
    __shared__ float sh_s[8], sh_ss[8];

    #pragma unroll
    for (int seg = 0; seg < 2; seg++) {
        float* p = row + seg * Cd;
        const float* gam = seg ? kg : qg;
        const float* bet = seg ? kb : qb;
        float x0 = p[tid], x1 = p[tid + 256];
        float s = x0 + x1;
        float ss = x0 * x0 + x1 * x1;
        #pragma unroll
        for (int o = 16; o; o >>= 1) {
            s  += __shfl_xor_sync(0xffffffffu, s, o);
            ss += __shfl_xor_sync(0xffffffffu, ss, o);
        }
        if (lane == 0) { sh_s[w] = s; sh_ss[w] = ss; }
        __syncthreads();
        float tot = 0.f, tot2 = 0.f;
        #pragma unroll
        for (int i = 0; i < 8; i++) { tot += sh_s[i]; tot2 += sh_ss[i]; }
        float mu = tot * (1.0f / 512.0f);
        float var = tot2 * (1.0f / 512.0f) - mu * mu;
        float rstd = rsqrtf(var + 1e-5f);
        p[tid]       = (x0 - mu) * rstd * gam[tid]       + bet[tid];
        p[tid + 256] = (x1 - mu) * rstd * gam[tid + 256] + bet[tid + 256];
        __syncthreads();
    }
}

// ---------------------------------------------------------------------------
// Fused attention per (b, h, 64-row q block).
//   scores[q,k] = q·k + q·rel_emb[|q-k|]_h  (rel term via P[q,delta] GEMM +
//   scatter-add, valid only in causal region where delta = q-k >= 0)
//   then causal softmax and att@v, all in shared memory.
// ---------------------------------------------------------------------------
#define QPITCH 68
#define SPITCH 516
#define ATTN_SMEM ((2 * 64 * QPITCH + 64 * SPITCH) * 4)   // 166912 bytes

__global__ __launch_bounds__(256) void attn_kernel(
    const float* __restrict__ qkv,
    const float* __restrict__ rel_emb,
    float* __restrict__ yout)
{
    const int blk = blockIdx.x;          // 512 blocks
    const int qb = blk & 7;
    const int h  = (blk >> 3) & 7;
    const int b  = blk >> 6;
    const int q0 = qb << 6;
    const int ntiles = qb + 1;
    const int kmax = ntiles << 6;

    extern __shared__ float sm[];
    float* q_s = sm;                    // [64 d][QPITCH]  (d-major)
    float* t_s = sm + 64 * QPITCH;      // tile buffer
    float* s_s = sm + 2 * 64 * QPITCH;  // [64 q][SPITCH] scores

    const int tid = threadIdx.x;
    const int tx = tid & 15, ty = tid >> 4;
    const int lane = tid & 31, warp = tid >> 5;

    // ---- load q block (LN'd), transposed to [d][qi] ----
    const float* qbase = qkv + (size_t)(b * Td + q0) * QKVN + h * HDd;
    #pragma unroll
    for (int i = 0; i < 4; i++) {
        int e = tid + i * 256;          // 1024 float4s
        int qi = e >> 4;
        int d4 = (e & 15) << 2;
        float4 v = *(const float4*)&qbase[(size_t)qi * QKVN + d4];
        q_s[(d4 + 0) * QPITCH + qi] = v.x;
        q_s[(d4 + 1) * QPITCH + qi] = v.y;
        q_s[(d4 + 2) * QPITCH + qi] = v.z;
        q_s[(d4 + 3) * QPITCH + qi] = v.w;
    }
    __syncthreads();

    // ---- Phase A: S = q @ k^T over causal k tiles ----
    for (int kt = 0; kt < ntiles; kt++) {
        const float* kbase = qkv + (size_t)(b * Td + (kt << 6)) * QKVN + Cd + h * HDd;
        #pragma unroll
        for (int i = 0; i < 4; i++) {
            int e = tid + i * 256;
            int ki = e >> 4;
            int d4 = (e & 15) << 2;
            float4 v = *(const float4*)&kbase[(size_t)ki * QKVN + d4];
            t_s[(d4 + 0) * QPITCH + ki] = v.x;
            t_s[(d4 + 1) * QPITCH + ki] = v.y;
            t_s[(d4 + 2) * QPITCH + ki] = v.z;
            t_s[(d4 + 3) * QPITCH + ki] = v.w;
        }
        __syncthreads();
        float acc[4][4] = {};
        #pragma unroll 8
        for (int d = 0; d < 64; d++) {
            float4 ra = *(const float4*)&q_s[d * QPITCH + (ty << 2)];
            float4 rb = *(const float4*)&t_s[d * QPITCH + (tx << 2)];
            float a_[4] = {ra.x, ra.y, ra.z, ra.w};
            float b_[4] = {rb.x, rb.y, rb.z, rb.w};
            #pragma unroll
            for (int i = 0; i < 4; i++)
                #pragma unroll
                for (int j = 0; j < 4; j++)
                    acc[i][j] += a_[i] * b_[j];
        }
        #pragma unroll
        for (int i = 0; i < 4; i++) {
            float4 o = make_float4(acc[i][0], acc[i][1], acc[i][2], acc[i][3]);
            *(float4*)&s_s[(size_t)((ty << 2) + i) * SPITCH + (kt << 6) + (tx << 2)] = o;
        }
        __syncthreads();
    }

    // ---- Phase B: P[q,delta] = q @ rel_h^T, scatter-add P[q,q-k] ----
    for (int dt = 0; dt < ntiles; dt++) {
        const float* rbase = rel_emb + (size_t)(dt << 6) * Cd + h * HDd;
        #pragma unroll
        for (int i = 0; i < 4; i++) {
            int e = tid + i * 256;
            int dl = e >> 4;
            int d4 = (e & 15) << 2;
            float4 v = *(const float4*)&rbase[(size_t)dl * Cd + d4];
            t_s[(d4 + 0) * QPITCH + dl] = v.x;
            t_s[(d4 + 1) * QPITCH + dl] = v.y;
            t_s[(d4 + 2) * QPITCH + dl] = v.z;
            t_s[(d4 + 3) * QPITCH + dl] = v.w;
        }
        __syncthreads();
        float acc[4][4] = {};
        #pragma unroll 8
        for (int d = 0; d < 64; d++) {
            float4 ra = *(const float4*)&q_s[d * QPITCH + (ty << 2)];
            float4 rb = *(const float4*)&t_s[d * QPITCH + (tx << 2)];
            float a_[4] = {ra.x, ra.y, ra.z, ra.w};
            float b_[4] = {rb.x, rb.y, rb.z, rb.w};
            #pragma unroll
            for (int i = 0; i < 4; i++)
                #pragma unroll
                for (int j = 0; j < 4; j++)
                    acc[i][j] += a_[i] * b_[j];
        }
        #pragma unroll
        for (int i = 0; i < 4; i++) {
            int qi = (ty << 2) + i;
            int qg = q0 + qi;
            #pragma unroll
            for (int j = 0; j < 4; j++) {
                int delta = (dt << 6) + (tx << 2) + j;
                int ki = qg - delta;
                if (ki >= 0) s_s[(size_t)qi * SPITCH + ki] += acc[i][j];
            }
        }
        __syncthreads();
    }

    // ---- Phase C: causal softmax (scale, max-sub, exp, normalize) ----
    const float scale = 0.125f;   // 1/sqrt(64)
    for (int r = warp * 8; r < warp * 8 + 8; r++) {
        const int qg = q0 + r;
        float mx = -1e30f;
        for (int col = lane; col < kmax; col += 32)
            if (col <= qg) mx = fmaxf(mx, s_s[(size_t)r * SPITCH + col]);
        #pragma unroll
        for (int o = 16; o; o >>= 1)
            mx = fmaxf(mx, __shfl_xor_sync(0xffffffffu, mx, o));
        mx *= scale;
        float sum = 0.f;
        for (int col = lane; col < kmax; col += 32) {
            float v = 0.f;
            if (col <= qg) {
                v = __expf(s_s[(size_t)r * SPITCH + col] * scale - mx);
                // use precise expf for accuracy margin
                v = expf(s_s[(size_t)r * SPITCH + col] * scale - mx);
                sum += v;
            }
            s_s[(size_t)r * SPITCH + col] = v;
        }
        #pragma unroll
        for (int o = 16; o; o >>= 1)
            sum += __shfl_xor_sync(0xffffffffu, sum, o);
        float inv = 1.0f / sum;
        for (int col = lane; col < kmax; col += 32)
            s_s[(size_t)r * SPITCH + col] *= inv;
    }
    __syncthreads();

    // ---- Phase D: out = att @ v ----
    float oacc[4][4] = {};
    for (int kt = 0; kt < ntiles; kt++) {
        const float* vbase = qkv + (size_t)(b * Td + (kt << 6)) * QKVN + 2 * Cd + h * HDd;
        #pragma unroll
        for (int i = 0; i < 4; i++) {
            int e = tid + i * 256;
            int ki = e >> 4;
            int d4 = (e & 15) << 2;
            float4 v = *(const float4*)&vbase[(size_t)ki * QKVN + d4];
            *(float4*)&t_s[ki * QPITCH + d4] = v;   // [ki][d]
        }
        __syncthreads();
        #pragma unroll 8
        for (int kk = 0; kk < 64; kk++) {
            float ra[4];
            #pragma unroll
            for (int i = 0; i < 4; i++)
                ra[i] = s_s[(size_t)((ty << 2) + i) * SPITCH + (kt << 6) + kk];
            float4 rb4 = *(const float4*)&t_s[kk * QPITCH + (tx << 2)];
            float b_[4] = {rb4.x, rb4.y, rb4.z, rb4.w};
            #pragma unroll
            for (int i = 0; i < 4; i++)
                #pragma unroll
                for (int j = 0; j < 4; j++)
                    oacc[i][j] += ra[i] * b_[j];
        }
        __syncthreads();
    }
    #pragma unroll
    for (int i = 0; i < 4; i++) {
        int trow = q0 + (ty << 2) + i;
        #pragma unroll
        for (int j = 0; j < 4; j++)
            yout[(size_t)(b * Td + trow) * Cd + h * HDd + (tx << 2) + j] = oacc[i][j];
    }
}

// ---------------------------------------------------------------------------
extern "C" void kernel_launch(void* const* d_in, const int* in_sizes, int n_in,
                              void* d_out, int out_size)
{
    const float* x      = (const float*)d_in[0];
    const float* w_attn = (const float*)d_in[1];
    const float* b_attn = (const float*)d_in[2];
    const float* w_proj = (const float*)d_in[3];
    const float* b_proj = (const float*)d_in[4];
    const float* qg     = (const float*)d_in[5];
    const float* qbeta  = (const float*)d_in[6];
    const float* kg     = (const float*)d_in[7];
    const float* kbeta  = (const float*)d_in[8];
    const float* rel    = (const float*)d_in[9];
    float* out = (float*)d_out;

    float *qkv_p, *y_p;
    cudaGetSymbolAddress((void**)&qkv_p, g_qkv);
    cudaGetSymbolAddress((void**)&y_p, g_y);

    cudaFuncSetAttribute(attn_kernel,
                         cudaFuncAttributeMaxDynamicSharedMemorySize, ATTN_SMEM);

    // 1) QKV projection
    {
        dim3 grid(QKVN / 64, Md / 64);
        sgemm_bias_kernel<<<grid, 256>>>(x, w_attn, b_attn, qkv_p, Cd, QKVN);
    }
    // 2) LayerNorm q,k in place
    ln_qk_kernel<<<Md, 256>>>(qkv_p, qg, qbeta, kg, kbeta);
    // 3) Fused attention
    attn_kernel<<<Bd * NHd * (Td / 64), 256, ATTN_SMEM>>>(qkv_p, rel, y_p);
    // 4) Output projection
    {
        dim3 grid(Cd / 64, Md / 64);
        sgemm_bias_kernel<<<grid, 256>>>(y_p, w_proj, b_proj, out, Cd, Cd);
    }
}

// round 4
// speedup vs baseline: 2.2262x; 2.2262x over previous
#include <cuda_runtime.h>

#define Bd 8
#define Td 512
#define Cd 512
#define NHd 8
#define HDd 64
#define Md (Bd * Td)            // 4096
#define QKVN (3 * Cd)           // 1536

__device__ float g_qkv[Md * QKVN];
__device__ float g_y[Md * Cd];

__device__ __forceinline__ unsigned f2tf(float f) {
    unsigned u; asm("cvt.rna.tf32.f32 %0, %1;" : "=r"(u) : "f"(f)); return u;
}
__device__ __forceinline__ void mma_tf32(float c[4],
    unsigned a0, unsigned a1, unsigned a2, unsigned a3,
    unsigned b0, unsigned b1)
{
    asm volatile(
        "mma.sync.aligned.m16n8k8.row.col.f32.tf32.tf32.f32 "
        "{%0,%1,%2,%3}, {%4,%5,%6,%7}, {%8,%9}, {%0,%1,%2,%3};"
        : "+f"(c[0]), "+f"(c[1]), "+f"(c[2]), "+f"(c[3])
        : "r"(a0), "r"(a1), "r"(a2), "r"(a3), "r"(b0), "r"(b1));
}

// ---------------------------------------------------------------------------
// tf32 SGEMM: out[m,n] = A[m,:]·W[n,:] + bias[n]
// BM=128, BN=64, BK=32, 256 threads, warps 4(M)x2(N), warp tile 32x32.
// ---------------------------------------------------------------------------
#define GPITCH 36
__global__ __launch_bounds__(256) void sgemm_bias_kernel(
    const float* __restrict__ A, const float* __restrict__ W,
    const float* __restrict__ bias, float* __restrict__ out,
    int Kdim, int Ndim)
{
    __shared__ unsigned As[128 * GPITCH];
    __shared__ unsigned Bs[64 * GPITCH];
    const int tid = threadIdx.x;
    const int lane = tid & 31, warp = tid >> 5;
    const int g = lane >> 2, tig = lane & 3;
    const int wm = (warp & 3) << 5;          // 0,32,64,96
    const int wn = (warp >> 2) << 5;         // 0,32
    const int m0 = blockIdx.y << 7, n0 = blockIdx.x << 6;

    const int lrow = tid >> 3;               // 0..31
    const int lk4 = (tid & 7) << 2;          // 0..28

    float c[2][4][4] = {};

    for (int k0 = 0; k0 < Kdim; k0 += 32) {
        #pragma unroll
        for (int i = 0; i < 4; i++) {
            int r = lrow + (i << 5);
            float4 v = *(const float4*)&A[(size_t)(m0 + r) * Kdim + k0 + lk4];
            *(uint4*)&As[r * GPITCH + lk4] =
                make_uint4(f2tf(v.x), f2tf(v.y), f2tf(v.z), f2tf(v.w));
        }
        #pragma unroll
        for (int i = 0; i < 2; i++) {
            int r = lrow + (i << 5);
            float4 v = *(const float4*)&W[(size_t)(n0 + r) * Kdim + k0 + lk4];
            *(uint4*)&Bs[r * GPITCH + lk4] =
                make_uint4(f2tf(v.x), f2tf(v.y), f2tf(v.z), f2tf(v.w));
        }
        __syncthreads();
        #pragma unroll
        for (int ks = 0; ks < 4; ks++) {
            const int ko = ks << 3;
            unsigned a[2][4];
            #pragma unroll
            for (int i = 0; i < 2; i++) {
                int mb = wm + (i << 4);
                a[i][0] = As[(mb + g) * GPITCH + ko + tig];
                a[i][1] = As[(mb + g + 8) * GPITCH + ko + tig];
                a[i][2] = As[(mb + g) * GPITCH + ko + tig + 4];
                a[i][3] = As[(mb + g + 8) * GPITCH + ko + tig + 4];
            }
            unsigned b[4][2];
            #pragma unroll
            for (int j = 0; j < 4; j++) {
                int nb = wn + (j << 3);
                b[j][0] = Bs[(nb + g) * GPITCH + ko + tig];
                b[j][1] = Bs[(nb + g) * GPITCH + ko + tig + 4];
            }
            #pragma unroll
            for (int i = 0; i < 2; i++)
                #pragma unroll
                for (int j = 0; j < 4; j++)
                    mma_tf32(c[i][j], a[i][0], a[i][1], a[i][2], a[i][3],
                             b[j][0], b[j][1]);
        }
        __syncthreads();
    }

    #pragma unroll
    for (int i = 0; i < 2; i++) {
        #pragma unroll
        for (int j = 0; j < 4; j++) {
            int row = m0 + wm + (i << 4) + g;
            int col = n0 + wn + (j << 3) + (tig << 1);
            float b0 = bias[col], b1 = bias[col + 1];
            *(float2*)&out[(size_t)row * Ndim + col] =
                make_float2(c[i][j][0] + b0, c[i][j][1] + b1);
            *(float2*)&out[(size_t)(row + 8) * Ndim + col] =
                make_float2(c[i][j][2] + b0, c[i][j][3] + b1);
        }
    }
}

// ---------------------------------------------------------------------------
// LayerNorm q,k segments in place. One block per (b,t) row.
// ---------------------------------------------------------------------------
__global__ __launch_bounds__(256) void ln_qk_kernel(
    float* __restrict__ qkv,
    const float* __restrict__ qg, const float* __restrict__ qb,
    const float* __restrict__ kg, const float* __restrict__ kb)
{
    const int bt = blockIdx.x;
    float* row = qkv + (size_t)bt * QKVN;
    const int tid = threadIdx.x;
    const int lane = tid & 31, w = tid >> 5;
    __shared__ float sh_s[8], sh_ss[8];

    #pragma unroll
    for (int seg = 0; seg < 2; seg++) {
        float* p = row + seg * Cd;
        const float* gam = seg ? kg : qg;
        const float* bet = seg ? kb : qb;
        float x0 = p[tid], x1 = p[tid + 256];
        float s = x0 + x1;
        float ss = x0 * x0 + x1 * x1;
        #pragma unroll
        for (int o = 16; o; o >>= 1) {
            s  += __shfl_xor_sync(0xffffffffu, s, o);
            ss += __shfl_xor_sync(0xffffffffu, ss, o);
        }
        if (lane == 0) { sh_s[w] = s; sh_ss[w] = ss; }
        __syncthreads();
        float tot = 0.f, tot2 = 0.f;
        #pragma unroll
        for (int i = 0; i < 8; i++) { tot += sh_s[i]; tot2 += sh_ss[i]; }
        float mu = tot * (1.0f / 512.0f);
        float var = tot2 * (1.0f / 512.0f) - mu * mu;
        float rstd = rsqrtf(var + 1e-5f);
        p[tid]       = (x0 - mu) * rstd * gam[tid]       + bet[tid];
        p[tid + 256] = (x1 - mu) * rstd * gam[tid + 256] + bet[tid + 256];
        __syncthreads();
    }
}

// ---------------------------------------------------------------------------
// Fused attention per (b, h, 64-row q block), tf32 mma for all three GEMMs.
// ---------------------------------------------------------------------------
#define QP 68
#define SP 516
#define ATTN_SMEM ((2 * 64 * QP + 64 * SP) * 4)   // 166912 bytes

__device__ __forceinline__ void load_tile_tf32(
    unsigned* __restrict__ dst, const float* __restrict__ src,
    int srcPitch, int tid)
{
    #pragma unroll
    for (int i = 0; i < 4; i++) {
        int e = tid + (i << 8);
        int r = e >> 4, c4 = (e & 15) << 2;
        float4 v = *(const float4*)&src[(size_t)r * srcPitch + c4];
        *(uint4*)&dst[r * QP + c4] =
            make_uint4(f2tf(v.x), f2tf(v.y), f2tf(v.z), f2tf(v.w));
    }
}

__global__ __launch_bounds__(256) void attn_kernel(
    const float* __restrict__ qkv,
    const float* __restrict__ rel_emb,
    float* __restrict__ yout)
{
    const int blk = blockIdx.x;
    const int qb = blk & 7;
    const int h  = (blk >> 3) & 7;
    const int b  = blk >> 6;
    const int q0 = qb << 6;
    const int ntiles = qb + 1;
    const int kmax = ntiles << 6;

    extern __shared__ float sm[];
    unsigned* q_s = (unsigned*)sm;                 // [64 q][QP]  tf32 bits
    unsigned* t_s = (unsigned*)(sm + 64 * QP);     // tile buffer (tf32 bits)
    float*    s_s = sm + 2 * 64 * QP;              // [64 q][SP]  scores fp32
    unsigned* s_u = (unsigned*)s_s;

    const int tid = threadIdx.x;
    const int lane = tid & 31, warp = tid >> 5;
    const int g = lane >> 2, tig = lane & 3;
    const int qm = (warp & 3) << 4;                // warp q rows (16)
    const int wn = (warp >> 2) << 5;               // warp n cols (32)

    // ---- q block (LN'd), row-major tf32 ----
    load_tile_tf32(q_s, qkv + (size_t)(b * Td + q0) * QKVN + h * HDd, QKVN, tid);
    __syncthreads();

    // ---- Phase A: S = q @ k^T over causal key tiles ----
    for (int kt = 0; kt < ntiles; kt++) {
        load_tile_tf32(t_s,
            qkv + (size_t)(b * Td + (kt << 6)) * QKVN + Cd + h * HDd, QKVN, tid);
        __syncthreads();
        float c[4][4] = {};
        #pragma unroll
        for (int ks = 0; ks < 8; ks++) {
            const int ko = ks << 3;
            unsigned a0 = q_s[(qm + g) * QP + ko + tig];
            unsigned a1 = q_s[(qm + g + 8) * QP + ko + tig];
            unsigned a2 = q_s[(qm + g) * QP + ko + tig + 4];
            unsigned a3 = q_s[(qm + g + 8) * QP + ko + tig + 4];
            #pragma unroll
            for (int j = 0; j < 4; j++) {
                unsigned b0 = t_s[(wn + (j << 3) + g) * QP + ko + tig];
                unsigned b1 = t_s[(wn + (j << 3) + g) * QP + ko + tig + 4];
                mma_tf32(c[j], a0, a1, a2, a3, b0, b1);
            }
        }
        #pragma unroll
        for (int j = 0; j < 4; j++) {
            int col = (kt << 6) + wn + (j << 3) + (tig << 1);
            *(float2*)&s_s[(qm + g) * SP + col]     = make_float2(c[j][0], c[j][1]);
            *(float2*)&s_s[(qm + g + 8) * SP + col] = make_float2(c[j][2], c[j][3]);
        }
        __syncthreads();
    }

    // ---- Phase B: P = q @ rel_h^T, scatter-add P[q, q-k] into scores ----
    for (int dt = 0; dt < ntiles; dt++) {
        load_tile_tf32(t_s, rel_emb + (size_t)(dt << 6) * Cd + h * HDd, Cd, tid);
        __syncthreads();
        float c[4][4] = {};
        #pragma unroll
        for (int ks = 0; ks < 8; ks++) {
            const int ko = ks << 3;
            unsigned a0 = q_s[(qm + g) * QP + ko + tig];
            unsigned a1 = q_s[(qm + g + 8) * QP + ko + tig];
            unsigned a2 = q_s[(qm + g) * QP + ko + tig + 4];
            unsigned a3 = q_s[(qm + g + 8) * QP + ko + tig + 4];
            #pragma unroll
            for (int j = 0; j < 4; j++) {
                unsigned b0 = t_s[(wn + (j << 3) + g) * QP + ko + tig];
                unsigned b1 = t_s[(wn + (j << 3) + g) * QP + ko + tig + 4];
                mma_tf32(c[j], a0, a1, a2, a3, b0, b1);
            }
        }
        #pragma unroll
        for (int j = 0; j < 4; j++) {
            int dglob = (dt << 6) + wn + (j << 3) + (tig << 1);
            int r0 = qm + g, r1 = qm + g + 8;
            int ki0 = (q0 + r0) - dglob;
            int ki1 = (q0 + r1) - dglob;
            if (ki0 >= 0)     s_s[r0 * SP + ki0]     += c[j][0];
            if (ki0 - 1 >= 0) s_s[r0 * SP + ki0 - 1] += c[j][1];
            if (ki1 >= 0)     s_s[r1 * SP + ki1]     += c[j][2];
            if (ki1 - 1 >= 0) s_s[r1 * SP + ki1 - 1] += c[j][3];
        }
        __syncthreads();
    }

    // ---- Phase C: causal softmax; write probabilities back as tf32 bits ----
    const float scale = 0.125f;
    for (int r = warp << 3; r < (warp << 3) + 8; r++) {
        const int qg_ = q0 + r;
        float mx = -1e30f;
        for (int col = lane; col < kmax; col += 32)
            if (col <= qg_) mx = fmaxf(mx, s_s[r * SP + col]);
        #pragma unroll
        for (int o = 16; o; o >>= 1)
            mx = fmaxf(mx, __shfl_xor_sync(0xffffffffu, mx, o));
        mx *= scale;
        float sum = 0.f;
        for (int col = lane; col < kmax; col += 32) {
            float v = 0.f;
            if (col <= qg_) {
                v = __expf(s_s[r * SP + col] * scale - mx);
                sum += v;
            }
            s_s[r * SP + col] = v;
        }
        #pragma unroll
        for (int o = 16; o; o >>= 1)
            sum += __shfl_xor_sync(0xffffffffu, sum, o);
        float inv = 1.0f / sum;
        for (int col = lane; col < kmax; col += 32)
            s_u[r * SP + col] = f2tf(s_s[r * SP + col] * inv);
    }
    __syncthreads();

    // ---- Phase D: O = P @ V (V tile stored transposed [d][key]) ----
    float o[4][4] = {};
    for (int kt = 0; kt < ntiles; kt++) {
        const float* vbase =
            qkv + (size_t)(b * Td + (kt << 6)) * QKVN + 2 * Cd + h * HDd;
        #pragma unroll
        for (int i = 0; i < 4; i++) {
            int e = tid + (i << 8);
            int key = e >> 4, d4 = (e & 15) << 2;
            float4 v = *(const float4*)&vbase[(size_t)key * QKVN + d4];
            t_s[(d4 + 0) * QP + key] = f2tf(v.x);
            t_s[(d4 + 1) * QP + key] = f2tf(v.y);
            t_s[(d4 + 2) * QP + key] = f2tf(v.z);
            t_s[(d4 + 3) * QP + key] = f2tf(v.w);
        }
        __syncthreads();
        #pragma unroll
        for (int ks = 0; ks < 8; ks++) {
            const int ko = (kt << 6) + (ks << 3);   // column in s_u
            const int kl = ks << 3;                 // key within tile
            unsigned a0 = s_u[(qm + g) * SP + ko + tig];
            unsigned a1 = s_u[(qm + g + 8) * SP + ko + tig];
            unsigned a2 = s_u[(qm + g) * SP + ko + tig + 4];
            unsigned a3 = s_u[(qm + g + 8) * SP + ko + tig + 4];
            #pragma unroll
            for (int j = 0; j < 4; j++) {
                unsigned b0 = t_s[(wn + (j << 3) + g) * QP + kl + tig];
                unsigned b1 = t_s[(wn + (j << 3) + g) * QP + kl + tig + 4];
                mma_tf32(o[j], a0, a1, a2, a3, b0, b1);
            }
        }
        __syncthreads();
    }
    #pragma unroll
    for (int j = 0; j < 4; j++) {
        int row = q0 + qm + g;
        int col = h * HDd + wn + (j << 3) + (tig << 1);
        *(float2*)&yout[(size_t)(b * Td + row) * Cd + col] =
            make_float2(o[j][0], o[j][1]);
        *(float2*)&yout[(size_t)(b * Td + row + 8) * Cd + col] =
            make_float2(o[j][2], o[j][3]);
    }
}

// ---------------------------------------------------------------------------
extern "C" void kernel_launch(void* const* d_in, const int* in_sizes, int n_in,
                              void* d_out, int out_size)
{
    const float* x      = (const float*)d_in[0];
    const float* w_attn = (const float*)d_in[1];
    const float* b_attn = (const float*)d_in[2];
    const float* w_proj = (const float*)d_in[3];
    const float* b_proj = (const float*)d_in[4];
    const float* qg     = (const float*)d_in[5];
    const float* qbeta  = (const float*)d_in[6];
    const float* kg     = (const float*)d_in[7];
    const float* kbeta  = (const float*)d_in[8];
    const float* rel    = (const float*)d_in[9];
    float* out = (float*)d_out;

    float *qkv_p, *y_p;
    cudaGetSymbolAddress((void**)&qkv_p, g_qkv);
    cudaGetSymbolAddress((void**)&y_p, g_y);

    cudaFuncSetAttribute(attn_kernel,
                         cudaFuncAttributeMaxDynamicSharedMemorySize, ATTN_SMEM);

    // 1) QKV projection
    {
        dim3 grid(QKVN / 64, Md / 128);
        sgemm_bias_kernel<<<grid, 256>>>(x, w_attn, b_attn, qkv_p, Cd, QKVN);
    }
    // 2) LayerNorm q,k in place
    ln_qk_kernel<<<Md, 256>>>(qkv_p, qg, qbeta, kg, kbeta);
    // 3) Fused attention
    attn_kernel<<<Bd * NHd * (Td / 64), 256, ATTN_SMEM>>>(qkv_p, rel, y_p);
    // 4) Output projection
    {
        dim3 grid(Cd / 64, Md / 128);
        sgemm_bias_kernel<<<grid, 256>>>(y_p, w_proj, b_proj, out, Cd, Cd);
    }
}